// round 1
// baseline (speedup 1.0000x reference)
#include <cuda_runtime.h>

#define SEQ 2048
#define DM 2048
#define NH 32
#define HD 64

// Scratch (static device allocations are allowed; cudaMalloc is not)
__device__ float g_Q[SEQ * DM];
__device__ float g_K[SEQ * DM];
__device__ float g_V[SEQ * DM];
__device__ float g_att[SEQ * DM];
__device__ float g_cos[SEQ * 32];
__device__ float g_sin[SEQ * 32];

// ---------------------------------------------------------------------------
// RoPE cos/sin table: freq[l][j] = l * 10000^(-j/32), j in [0,32)
// ---------------------------------------------------------------------------
__global__ void rope_table_kernel() {
    int idx = blockIdx.x * blockDim.x + threadIdx.x;
    if (idx >= SEQ * 32) return;
    int l = idx >> 5;
    int j = idx & 31;
    float invf = powf(10000.0f, -(float)j * (1.0f / 32.0f));
    float fr = (float)l * invf;
    g_cos[idx] = cosf(fr);
    g_sin[idx] = sinf(fr);
}

// ---------------------------------------------------------------------------
// RoPE apply, in place on g_Q (blockIdx.y==0) or g_K (blockIdx.y==1).
// One thread handles one (position, head): reads 64 floats, rotates pairs,
// writes back in the reference's concatenated-halves layout.
//   out[j]    = x[2j]*cos - x[2j+1]*sin
//   out[32+j] = x[2j]*sin + x[2j+1]*cos
// ---------------------------------------------------------------------------
__global__ void __launch_bounds__(256) rope_apply_kernel() {
    int t = blockIdx.x * blockDim.x + threadIdx.x;
    if (t >= SEQ * NH) return;
    int l = t >> 5;
    int h = t & 31;
    float* base = (blockIdx.y == 0 ? g_Q : g_K) + (size_t)l * DM + h * HD;

    float v[64];
#pragma unroll
    for (int i = 0; i < 16; i++)
        *(float4*)(v + 4 * i) = *(const float4*)(base + 4 * i);

#pragma unroll
    for (int j = 0; j < 32; j++) {
        float c = g_cos[l * 32 + j];
        float s = g_sin[l * 32 + j];
        float x1 = v[2 * j];
        float x2 = v[2 * j + 1];
        v[2 * j]     = x1 * c - x2 * s;   // -> out[j]
        v[2 * j + 1] = x1 * s + x2 * c;   // -> out[32+j]
    }
#pragma unroll
    for (int j = 0; j < 32; j++) {
        base[j]      = v[2 * j];
        base[32 + j] = v[2 * j + 1];
    }
}

// ---------------------------------------------------------------------------
// C[M,N] = A[M,K] * B[N,K]^T, M=N=K=2048 (both operands row-major,
// K-contiguous -> "NT" gemm). 128x128 tile, BK=8, 256 threads, each thread
// computes a split 8x8 microtile (rows ty*4..+3 and 64+ty*4..+3, cols
// tx*4..+3 and 64+tx*4..+3) so smem float4 reads are at most 2-way conflicted.
// ---------------------------------------------------------------------------
__global__ void __launch_bounds__(256) gemm_nt_kernel(float* __restrict__ C,
                                                      const float* __restrict__ A,
                                                      const float* __restrict__ B) {
    __shared__ float As[8][128];
    __shared__ float Bs[8][128];
    int tid = threadIdx.x;
    int bm = blockIdx.y * 128;
    int bn = blockIdx.x * 128;
    int tx = tid & 15;
    int ty = tid >> 4;
    int lr = tid >> 1;            // 0..127 : row within tile
    int lc = (tid & 1) * 4;       // 0 or 4 : k-offset of the float4

    const float* Ap = A + (size_t)(bm + lr) * DM + lc;
    const float* Bp = B + (size_t)(bn + lr) * DM + lc;

    float acc[8][8];
#pragma unroll
    for (int i = 0; i < 8; i++)
#pragma unroll
        for (int j = 0; j < 8; j++) acc[i][j] = 0.0f;

    for (int k0 = 0; k0 < DM; k0 += 8) {
        float4 av = *(const float4*)(Ap + k0);
        float4 bv = *(const float4*)(Bp + k0);
        __syncthreads();
        As[lc + 0][lr] = av.x; As[lc + 1][lr] = av.y;
        As[lc + 2][lr] = av.z; As[lc + 3][lr] = av.w;
        Bs[lc + 0][lr] = bv.x; Bs[lc + 1][lr] = bv.y;
        Bs[lc + 2][lr] = bv.z; Bs[lc + 3][lr] = bv.w;
        __syncthreads();
#pragma unroll
        for (int kk = 0; kk < 8; kk++) {
            float a[8], b[8];
            *(float4*)(a)     = *(const float4*)&As[kk][ty * 4];
            *(float4*)(a + 4) = *(const float4*)&As[kk][64 + ty * 4];
            *(float4*)(b)     = *(const float4*)&Bs[kk][tx * 4];
            *(float4*)(b + 4) = *(const float4*)&Bs[kk][64 + tx * 4];
#pragma unroll
            for (int i = 0; i < 8; i++)
#pragma unroll
                for (int j = 0; j < 8; j++)
                    acc[i][j] = fmaf(a[i], b[j], acc[i][j]);
        }
    }

#pragma unroll
    for (int i = 0; i < 8; i++) {
        int row = bm + ((i < 4) ? (ty * 4 + i) : (64 + ty * 4 + (i - 4)));
        float4 v0 = make_float4(acc[i][0], acc[i][1], acc[i][2], acc[i][3]);
        float4 v1 = make_float4(acc[i][4], acc[i][5], acc[i][6], acc[i][7]);
        *(float4*)&C[(size_t)row * DM + bn + tx * 4]      = v0;
        *(float4*)&C[(size_t)row * DM + bn + 64 + tx * 4] = v1;
    }
}

// ---------------------------------------------------------------------------
// Flash attention, fp32. One block = (head, 64-query tile). 256 threads as a
// 16x16 grid; each thread owns a 4x4 S/P microtile and a 4(query)x4(dim) O
// accumulator. Online softmax with 16-lane butterfly reductions (the 16 tx
// lanes of a ty share the same 4 query rows; xor<=8 stays in the group and
// gives bitwise-identical results on all lanes).
// Smem: Qs [d][r] stride 65, KPs [d][c] stride 65 (reused for P as [r][c]
// stride 65), Vs [k][d] stride 64 -> every inner LDS is <=2-way conflicted,
// all smem stores from loads are conflict-free & coalesced from gmem.
// ---------------------------------------------------------------------------
__global__ void __launch_bounds__(256) attn_kernel(const int* __restrict__ mask) {
    extern __shared__ float sm[];
    float* Qs  = sm;               // 64*65
    float* KPs = sm + 64 * 65;     // 64*65 (K as [d][c], then P as [r][c])
    float* Vs  = sm + 2 * 64 * 65; // 64*64

    int tid = threadIdx.x;
    int tx = tid & 15;
    int ty = tid >> 4;
    int qt = blockIdx.x;
    int h = blockIdx.y;
    int q0 = qt * 64;

    const float* Qg = g_Q + (size_t)q0 * DM + h * HD;
    for (int idx = tid; idx < 4096; idx += 256) {
        int d = idx & 63, r = idx >> 6;
        Qs[d * 65 + r] = Qg[(size_t)r * DM + d];
    }

    float m_[4], l_[4], o_[4][4];
#pragma unroll
    for (int i = 0; i < 4; i++) {
        m_[i] = -3.0e38f;
        l_[i] = 0.0f;
#pragma unroll
        for (int j = 0; j < 4; j++) o_[i][j] = 0.0f;
    }

    for (int kt = 0; kt < 32; kt++) {
        int k0 = kt * 64;
        const float* Kg = g_K + (size_t)k0 * DM + h * HD;
        const float* Vg = g_V + (size_t)k0 * DM + h * HD;

        __syncthreads();  // protect KPs/Vs from previous iteration's readers
        for (int idx = tid; idx < 4096; idx += 256) {
            int d = idx & 63, r = idx >> 6;
            KPs[d * 65 + r] = Kg[(size_t)r * DM + d];
            Vs[r * 64 + d]  = Vg[(size_t)r * DM + d];
        }
        __syncthreads();

        // S = Q . K^T for this tile
        float s[4][4];
#pragma unroll
        for (int i = 0; i < 4; i++)
#pragma unroll
            for (int j = 0; j < 4; j++) s[i][j] = 0.0f;

#pragma unroll 8
        for (int kk = 0; kk < 64; kk++) {
            float a[4], b[4];
#pragma unroll
            for (int i = 0; i < 4; i++) a[i] = Qs[kk * 65 + ty * 4 + i];
#pragma unroll
            for (int j = 0; j < 4; j++) b[j] = KPs[kk * 65 + tx * 4 + j];
#pragma unroll
            for (int i = 0; i < 4; i++)
#pragma unroll
                for (int j = 0; j < 4; j++)
                    s[i][j] = fmaf(a[i], b[j], s[i][j]);
        }

        // scale + mask (mask is per key position)
#pragma unroll
        for (int j = 0; j < 4; j++) {
            int mv = mask[k0 + tx * 4 + j];
#pragma unroll
            for (int i = 0; i < 4; i++)
                s[i][j] = mv ? s[i][j] * 0.125f : -1.0e9f;
        }

        __syncthreads();  // all reads of KPs-as-K done; safe to write P into it

        // online softmax, per query row
#pragma unroll
        for (int i = 0; i < 4; i++) {
            float rmax = fmaxf(fmaxf(s[i][0], s[i][1]), fmaxf(s[i][2], s[i][3]));
#pragma unroll
            for (int o = 8; o > 0; o >>= 1)
                rmax = fmaxf(rmax, __shfl_xor_sync(0xffffffffu, rmax, o));
            float mn = fmaxf(m_[i], rmax);
            float corr = expf(m_[i] - mn);
            float ps = 0.0f;
#pragma unroll
            for (int j = 0; j < 4; j++) {
                s[i][j] = expf(s[i][j] - mn);
                ps += s[i][j];
            }
#pragma unroll
            for (int o = 8; o > 0; o >>= 1)
                ps += __shfl_xor_sync(0xffffffffu, ps, o);
            l_[i] = l_[i] * corr + ps;
            m_[i] = mn;
#pragma unroll
            for (int j = 0; j < 4; j++) o_[i][j] *= corr;
            // store P tile
#pragma unroll
            for (int j = 0; j < 4; j++)
                KPs[(ty * 4 + i) * 65 + tx * 4 + j] = s[i][j];
        }
        __syncthreads();

        // O += P . V
#pragma unroll 8
        for (int k = 0; k < 64; k++) {
            float a[4], b[4];
#pragma unroll
            for (int i = 0; i < 4; i++) a[i] = KPs[(ty * 4 + i) * 65 + k];
#pragma unroll
            for (int j = 0; j < 4; j++) b[j] = Vs[k * 64 + tx * 4 + j];
#pragma unroll
            for (int i = 0; i < 4; i++)
#pragma unroll
                for (int j = 0; j < 4; j++)
                    o_[i][j] = fmaf(a[i], b[j], o_[i][j]);
        }
    }

    float* Og = g_att + (size_t)q0 * DM + h * HD;
#pragma unroll
    for (int i = 0; i < 4; i++) {
        float inv = 1.0f / l_[i];
        float4 v = make_float4(o_[i][0] * inv, o_[i][1] * inv,
                               o_[i][2] * inv, o_[i][3] * inv);
        *(float4*)&Og[(size_t)(ty * 4 + i) * DM + tx * 4] = v;
    }
}

// ---------------------------------------------------------------------------
// launch
// ---------------------------------------------------------------------------
extern "C" void kernel_launch(void* const* d_in, const int* in_sizes, int n_in,
                              void* d_out, int out_size) {
    const float* x    = (const float*)d_in[0];
    const int*   mask = (const int*)d_in[1];
    const float* Wq   = (const float*)d_in[2];
    const float* Wk   = (const float*)d_in[3];
    const float* Wv   = (const float*)d_in[4];
    const float* Wo   = (const float*)d_in[5];
    float* out = (float*)d_out;

    float *Q, *K, *V, *att;
    cudaGetSymbolAddress((void**)&Q, g_Q);
    cudaGetSymbolAddress((void**)&K, g_K);
    cudaGetSymbolAddress((void**)&V, g_V);
    cudaGetSymbolAddress((void**)&att, g_att);

    dim3 gg(16, 16);
    gemm_nt_kernel<<<gg, 256>>>(Q, x, Wq);
    gemm_nt_kernel<<<gg, 256>>>(K, x, Wk);
    gemm_nt_kernel<<<gg, 256>>>(V, x, Wv);

    rope_table_kernel<<<(SEQ * 32 + 255) / 256, 256>>>();
    rope_apply_kernel<<<dim3((SEQ * NH + 255) / 256, 2), 256>>>();

    const int attn_smem = (2 * 64 * 65 + 64 * 64) * (int)sizeof(float);  // 49664
    cudaFuncSetAttribute(attn_kernel, cudaFuncAttributeMaxDynamicSharedMemorySize,
                         attn_smem);
    attn_kernel<<<dim3(32, 32), 256, attn_smem>>>(mask);

    gemm_nt_kernel<<<gg, 256>>>(out, att, Wo);
}

// round 2
// speedup vs baseline: 1.7182x; 1.7182x over previous
#include <cuda_runtime.h>

#define SEQ 2048
#define DM 2048
#define NH 32
#define HD 64

// Scratch (static device allocations are allowed; cudaMalloc is not)
__device__ float g_Q[SEQ * DM];
__device__ float g_K[SEQ * DM];
__device__ float g_V[SEQ * DM];
__device__ float g_att[SEQ * DM];
__device__ float g_cos[SEQ * 32];
__device__ float g_sin[SEQ * 32];

// ---------------------------------------------------------------------------
// tf32 helpers
// ---------------------------------------------------------------------------
__device__ __forceinline__ unsigned f2tf32(float f) {
    unsigned r;
    asm("cvt.rna.tf32.f32 %0, %1;" : "=r"(r) : "f"(f));
    return r;
}

__device__ __forceinline__ void mma_tf32(float* c, const unsigned* a, const unsigned* b) {
    asm volatile(
        "mma.sync.aligned.m16n8k8.row.col.f32.tf32.tf32.f32 "
        "{%0,%1,%2,%3}, {%4,%5,%6,%7}, {%8,%9}, {%0,%1,%2,%3};"
        : "+f"(c[0]), "+f"(c[1]), "+f"(c[2]), "+f"(c[3])
        : "r"(a[0]), "r"(a[1]), "r"(a[2]), "r"(a[3]), "r"(b[0]), "r"(b[1]));
}

// ---------------------------------------------------------------------------
// RoPE cos/sin table: freq[l][j] = l * 10000^(-j/32), j in [0,32)
// ---------------------------------------------------------------------------
__global__ void rope_table_kernel() {
    int idx = blockIdx.x * blockDim.x + threadIdx.x;
    if (idx >= SEQ * 32) return;
    int l = idx >> 5;
    int j = idx & 31;
    float invf = powf(10000.0f, -(float)j * (1.0f / 32.0f));
    float fr = (float)l * invf;
    g_cos[idx] = cosf(fr);
    g_sin[idx] = sinf(fr);
}

// ---------------------------------------------------------------------------
// RoPE apply, in place on g_Q (blockIdx.y==0) or g_K (blockIdx.y==1).
//   out[j]    = x[2j]*cos - x[2j+1]*sin
//   out[32+j] = x[2j]*sin + x[2j+1]*cos
// ---------------------------------------------------------------------------
__global__ void __launch_bounds__(256) rope_apply_kernel() {
    int t = blockIdx.x * blockDim.x + threadIdx.x;
    if (t >= SEQ * NH) return;
    int l = t >> 5;
    int h = t & 31;
    float* base = (blockIdx.y == 0 ? g_Q : g_K) + (size_t)l * DM + h * HD;

    float v[64];
#pragma unroll
    for (int i = 0; i < 16; i++)
        *(float4*)(v + 4 * i) = *(const float4*)(base + 4 * i);

#pragma unroll
    for (int j = 0; j < 32; j++) {
        float c = g_cos[l * 32 + j];
        float s = g_sin[l * 32 + j];
        float x1 = v[2 * j];
        float x2 = v[2 * j + 1];
        v[2 * j]     = x1 * c - x2 * s;   // -> out[j]
        v[2 * j + 1] = x1 * s + x2 * c;   // -> out[32+j]
    }
#pragma unroll
    for (int j = 0; j < 32; j++) {
        base[j]      = v[2 * j];
        base[32 + j] = v[2 * j + 1];
    }
}

// ---------------------------------------------------------------------------
// TF32 tensor-core GEMM body: C[M,N] = A[M,K] * B[N,K]^T, M=N=K=2048.
// Block = 128x128x(BK=32), 256 threads = 8 warps as 4(m) x 2(n); each warp
// owns a 32x64 tile = 2(m16) x 8(n8) mma fragments. Smem stride 36 makes
// every fragment LDS conflict-free: bank = (4*group + tg) mod 32 covers all
// 32 banks exactly once per warp.
// ---------------------------------------------------------------------------
#define SST 36

__device__ __forceinline__ void gemm_body(float* __restrict__ C,
                                          const float* __restrict__ A,
                                          const float* __restrict__ B) {
    __shared__ unsigned As[128 * SST];
    __shared__ unsigned Bs[128 * SST];

    int tid = threadIdx.x;
    int lane = tid & 31, warp = tid >> 5;
    int wm = warp >> 1, wn = warp & 1;
    int g = lane >> 2, tg = lane & 3;
    int bm = blockIdx.y * 128, bn = blockIdx.x * 128;

    int lrow = tid >> 3;        // 0..31
    int lcol = (tid & 7) * 4;   // 0,4,..,28

    float acc[2][8][4];
#pragma unroll
    for (int mi = 0; mi < 2; mi++)
#pragma unroll
        for (int ni = 0; ni < 8; ni++)
#pragma unroll
            for (int j = 0; j < 4; j++) acc[mi][ni][j] = 0.0f;

    for (int k0 = 0; k0 < DM; k0 += 32) {
        __syncthreads();
#pragma unroll
        for (int p = 0; p < 4; p++) {
            int row = lrow + p * 32;
            float4 av = *(const float4*)&A[(size_t)(bm + row) * DM + k0 + lcol];
            float4 bv = *(const float4*)&B[(size_t)(bn + row) * DM + k0 + lcol];
            unsigned* as = &As[row * SST + lcol];
            as[0] = f2tf32(av.x); as[1] = f2tf32(av.y);
            as[2] = f2tf32(av.z); as[3] = f2tf32(av.w);
            unsigned* bs = &Bs[row * SST + lcol];
            bs[0] = f2tf32(bv.x); bs[1] = f2tf32(bv.y);
            bs[2] = f2tf32(bv.z); bs[3] = f2tf32(bv.w);
        }
        __syncthreads();

#pragma unroll
        for (int k8 = 0; k8 < 4; k8++) {
            int c = k8 * 8 + tg;
            unsigned afr[2][4], bfr[8][2];
#pragma unroll
            for (int mi = 0; mi < 2; mi++) {
                int r = wm * 32 + mi * 16 + g;
                afr[mi][0] = As[r * SST + c];
                afr[mi][1] = As[(r + 8) * SST + c];
                afr[mi][2] = As[r * SST + c + 4];
                afr[mi][3] = As[(r + 8) * SST + c + 4];
            }
#pragma unroll
            for (int ni = 0; ni < 8; ni++) {
                int n = wn * 64 + ni * 8 + g;
                bfr[ni][0] = Bs[n * SST + c];
                bfr[ni][1] = Bs[n * SST + c + 4];
            }
#pragma unroll
            for (int mi = 0; mi < 2; mi++)
#pragma unroll
                for (int ni = 0; ni < 8; ni++)
                    mma_tf32(acc[mi][ni], afr[mi], bfr[ni]);
        }
    }

#pragma unroll
    for (int mi = 0; mi < 2; mi++)
#pragma unroll
        for (int ni = 0; ni < 8; ni++) {
            int r0 = bm + wm * 32 + mi * 16 + g;
            int cc = bn + wn * 64 + ni * 8 + 2 * tg;
            *(float2*)&C[(size_t)r0 * DM + cc] =
                make_float2(acc[mi][ni][0], acc[mi][ni][1]);
            *(float2*)&C[(size_t)(r0 + 8) * DM + cc] =
                make_float2(acc[mi][ni][2], acc[mi][ni][3]);
        }
}

// Fused QKV projection: grid.z selects the weight / destination pair.
__global__ void __launch_bounds__(256) gemm_qkv_kernel(const float* __restrict__ x,
                                                       const float* __restrict__ Wq,
                                                       const float* __restrict__ Wk,
                                                       const float* __restrict__ Wv) {
    const float* B;
    float* C;
    if (blockIdx.z == 0)      { B = Wq; C = g_Q; }
    else if (blockIdx.z == 1) { B = Wk; C = g_K; }
    else                      { B = Wv; C = g_V; }
    gemm_body(C, x, B);
}

__global__ void __launch_bounds__(256) gemm_out_kernel(float* __restrict__ C,
                                                       const float* __restrict__ Wo) {
    gemm_body(C, g_att, Wo);
}

// ---------------------------------------------------------------------------
// Flash attention, fp32 SIMT (unchanged from round 0).
// ---------------------------------------------------------------------------
__global__ void __launch_bounds__(256) attn_kernel(const int* __restrict__ mask) {
    extern __shared__ float sm[];
    float* Qs  = sm;               // 64*65
    float* KPs = sm + 64 * 65;     // 64*65 (K as [d][c], then P as [r][c])
    float* Vs  = sm + 2 * 64 * 65; // 64*64

    int tid = threadIdx.x;
    int tx = tid & 15;
    int ty = tid >> 4;
    int qt = blockIdx.x;
    int h = blockIdx.y;
    int q0 = qt * 64;

    const float* Qg = g_Q + (size_t)q0 * DM + h * HD;
    for (int idx = tid; idx < 4096; idx += 256) {
        int d = idx & 63, r = idx >> 6;
        Qs[d * 65 + r] = Qg[(size_t)r * DM + d];
    }

    float m_[4], l_[4], o_[4][4];
#pragma unroll
    for (int i = 0; i < 4; i++) {
        m_[i] = -3.0e38f;
        l_[i] = 0.0f;
#pragma unroll
        for (int j = 0; j < 4; j++) o_[i][j] = 0.0f;
    }

    for (int kt = 0; kt < 32; kt++) {
        int k0 = kt * 64;
        const float* Kg = g_K + (size_t)k0 * DM + h * HD;
        const float* Vg = g_V + (size_t)k0 * DM + h * HD;

        __syncthreads();
        for (int idx = tid; idx < 4096; idx += 256) {
            int d = idx & 63, r = idx >> 6;
            KPs[d * 65 + r] = Kg[(size_t)r * DM + d];
            Vs[r * 64 + d]  = Vg[(size_t)r * DM + d];
        }
        __syncthreads();

        float s[4][4];
#pragma unroll
        for (int i = 0; i < 4; i++)
#pragma unroll
            for (int j = 0; j < 4; j++) s[i][j] = 0.0f;

#pragma unroll 8
        for (int kk = 0; kk < 64; kk++) {
            float a[4], b[4];
#pragma unroll
            for (int i = 0; i < 4; i++) a[i] = Qs[kk * 65 + ty * 4 + i];
#pragma unroll
            for (int j = 0; j < 4; j++) b[j] = KPs[kk * 65 + tx * 4 + j];
#pragma unroll
            for (int i = 0; i < 4; i++)
#pragma unroll
                for (int j = 0; j < 4; j++)
                    s[i][j] = fmaf(a[i], b[j], s[i][j]);
        }

#pragma unroll
        for (int j = 0; j < 4; j++) {
            int mv = mask[k0 + tx * 4 + j];
#pragma unroll
            for (int i = 0; i < 4; i++)
                s[i][j] = mv ? s[i][j] * 0.125f : -1.0e9f;
        }

        __syncthreads();

#pragma unroll
        for (int i = 0; i < 4; i++) {
            float rmax = fmaxf(fmaxf(s[i][0], s[i][1]), fmaxf(s[i][2], s[i][3]));
#pragma unroll
            for (int o = 8; o > 0; o >>= 1)
                rmax = fmaxf(rmax, __shfl_xor_sync(0xffffffffu, rmax, o));
            float mn = fmaxf(m_[i], rmax);
            float corr = expf(m_[i] - mn);
            float ps = 0.0f;
#pragma unroll
            for (int j = 0; j < 4; j++) {
                s[i][j] = expf(s[i][j] - mn);
                ps += s[i][j];
            }
#pragma unroll
            for (int o = 8; o > 0; o >>= 1)
                ps += __shfl_xor_sync(0xffffffffu, ps, o);
            l_[i] = l_[i] * corr + ps;
            m_[i] = mn;
#pragma unroll
            for (int j = 0; j < 4; j++) o_[i][j] *= corr;
#pragma unroll
            for (int j = 0; j < 4; j++)
                KPs[(ty * 4 + i) * 65 + tx * 4 + j] = s[i][j];
        }
        __syncthreads();

#pragma unroll 8
        for (int k = 0; k < 64; k++) {
            float a[4], b[4];
#pragma unroll
            for (int i = 0; i < 4; i++) a[i] = KPs[(ty * 4 + i) * 65 + k];
#pragma unroll
            for (int j = 0; j < 4; j++) b[j] = Vs[k * 64 + tx * 4 + j];
#pragma unroll
            for (int i = 0; i < 4; i++)
#pragma unroll
                for (int j = 0; j < 4; j++)
                    o_[i][j] = fmaf(a[i], b[j], o_[i][j]);
        }
    }

    float* Og = g_att + (size_t)q0 * DM + h * HD;
#pragma unroll
    for (int i = 0; i < 4; i++) {
        float inv = 1.0f / l_[i];
        float4 v = make_float4(o_[i][0] * inv, o_[i][1] * inv,
                               o_[i][2] * inv, o_[i][3] * inv);
        *(float4*)&Og[(size_t)(ty * 4 + i) * DM + tx * 4] = v;
    }
}

// ---------------------------------------------------------------------------
// launch
// ---------------------------------------------------------------------------
extern "C" void kernel_launch(void* const* d_in, const int* in_sizes, int n_in,
                              void* d_out, int out_size) {
    const float* x    = (const float*)d_in[0];
    const int*   mask = (const int*)d_in[1];
    const float* Wq   = (const float*)d_in[2];
    const float* Wk   = (const float*)d_in[3];
    const float* Wv   = (const float*)d_in[4];
    const float* Wo   = (const float*)d_in[5];
    float* out = (float*)d_out;

    gemm_qkv_kernel<<<dim3(16, 16, 3), 256>>>(x, Wq, Wk, Wv);

    rope_table_kernel<<<(SEQ * 32 + 255) / 256, 256>>>();
    rope_apply_kernel<<<dim3((SEQ * NH + 255) / 256, 2), 256>>>();

    const int attn_smem = (2 * 64 * 65 + 64 * 64) * (int)sizeof(float);  // 49664
    cudaFuncSetAttribute(attn_kernel, cudaFuncAttributeMaxDynamicSharedMemorySize,
                         attn_smem);
    attn_kernel<<<dim3(32, 32), 256, attn_smem>>>(mask);

    gemm_out_kernel<<<dim3(16, 16), 256>>>(out, Wo);
}

// round 3
// speedup vs baseline: 1.9403x; 1.1292x over previous
#include <cuda_runtime.h>

#define SEQ 2048
#define DM 2048
#define NH 32
#define HD 64

// Scratch (static device allocations are allowed; cudaMalloc is not)
__device__ float g_Q[SEQ * DM];
__device__ float g_K[SEQ * DM];
__device__ float g_V[SEQ * DM];
__device__ float g_att[SEQ * DM];
__device__ float g_cos[SEQ * 32];
__device__ float g_sin[SEQ * 32];

// ---------------------------------------------------------------------------
// tf32 helpers
// ---------------------------------------------------------------------------
__device__ __forceinline__ unsigned f2tf32(float f) {
    unsigned r;
    asm("cvt.rna.tf32.f32 %0, %1;" : "=r"(r) : "f"(f));
    return r;
}

__device__ __forceinline__ void mma_tf32(float* c, const unsigned* a, const unsigned* b) {
    asm volatile(
        "mma.sync.aligned.m16n8k8.row.col.f32.tf32.tf32.f32 "
        "{%0,%1,%2,%3}, {%4,%5,%6,%7}, {%8,%9}, {%0,%1,%2,%3};"
        : "+f"(c[0]), "+f"(c[1]), "+f"(c[2]), "+f"(c[3])
        : "r"(a[0]), "r"(a[1]), "r"(a[2]), "r"(a[3]), "r"(b[0]), "r"(b[1]));
}

// FMA-pipe exp2 (no MUFU): 2^y, y clamped at -126. ~1.5e-6 rel error.
__device__ __forceinline__ float exp2p(float y) {
    y = fmaxf(y, -126.0f);
    float z = y + 12582912.0f;                 // round-to-nearest int
    int i = __float_as_int(z) - 0x4B400000;
    float f = y - (z - 12582912.0f);           // f in [-0.5, 0.5]
    float p = 1.3534384e-3f;
    p = fmaf(p, f, 9.6181291e-3f);
    p = fmaf(p, f, 5.5504109e-2f);
    p = fmaf(p, f, 2.4022650e-1f);
    p = fmaf(p, f, 6.9314718e-1f);
    p = fmaf(p, f, 1.0f);
    return __int_as_float(__float_as_int(p) + (i << 23));
}

#define LOG2E 1.4426950408889634f

// ---------------------------------------------------------------------------
// RoPE cos/sin table
// ---------------------------------------------------------------------------
__global__ void rope_table_kernel() {
    int idx = blockIdx.x * blockDim.x + threadIdx.x;
    if (idx >= SEQ * 32) return;
    int l = idx >> 5;
    int j = idx & 31;
    float invf = powf(10000.0f, -(float)j * (1.0f / 32.0f));
    float fr = (float)l * invf;
    g_cos[idx] = cosf(fr);
    g_sin[idx] = sinf(fr);
}

// ---------------------------------------------------------------------------
// RoPE apply (concatenated-halves layout)
// ---------------------------------------------------------------------------
__global__ void __launch_bounds__(256) rope_apply_kernel() {
    int t = blockIdx.x * blockDim.x + threadIdx.x;
    if (t >= SEQ * NH) return;
    int l = t >> 5;
    int h = t & 31;
    float* base = (blockIdx.y == 0 ? g_Q : g_K) + (size_t)l * DM + h * HD;

    float v[64];
#pragma unroll
    for (int i = 0; i < 16; i++)
        *(float4*)(v + 4 * i) = *(const float4*)(base + 4 * i);

#pragma unroll
    for (int j = 0; j < 32; j++) {
        float c = g_cos[l * 32 + j];
        float s = g_sin[l * 32 + j];
        float x1 = v[2 * j];
        float x2 = v[2 * j + 1];
        v[2 * j]     = x1 * c - x2 * s;
        v[2 * j + 1] = x1 * s + x2 * c;
    }
#pragma unroll
    for (int j = 0; j < 32; j++) {
        base[j]      = v[2 * j];
        base[32 + j] = v[2 * j + 1];
    }
}

// ---------------------------------------------------------------------------
// TF32 tensor-core GEMM (unchanged from round 2)
// ---------------------------------------------------------------------------
#define SST 36

__device__ __forceinline__ void gemm_body(float* __restrict__ C,
                                          const float* __restrict__ A,
                                          const float* __restrict__ B) {
    __shared__ unsigned As[128 * SST];
    __shared__ unsigned Bs[128 * SST];

    int tid = threadIdx.x;
    int lane = tid & 31, warp = tid >> 5;
    int wm = warp >> 1, wn = warp & 1;
    int g = lane >> 2, tg = lane & 3;
    int bm = blockIdx.y * 128, bn = blockIdx.x * 128;

    int lrow = tid >> 3;
    int lcol = (tid & 7) * 4;

    float acc[2][8][4];
#pragma unroll
    for (int mi = 0; mi < 2; mi++)
#pragma unroll
        for (int ni = 0; ni < 8; ni++)
#pragma unroll
            for (int j = 0; j < 4; j++) acc[mi][ni][j] = 0.0f;

    for (int k0 = 0; k0 < DM; k0 += 32) {
        __syncthreads();
#pragma unroll
        for (int p = 0; p < 4; p++) {
            int row = lrow + p * 32;
            float4 av = *(const float4*)&A[(size_t)(bm + row) * DM + k0 + lcol];
            float4 bv = *(const float4*)&B[(size_t)(bn + row) * DM + k0 + lcol];
            unsigned* as = &As[row * SST + lcol];
            as[0] = f2tf32(av.x); as[1] = f2tf32(av.y);
            as[2] = f2tf32(av.z); as[3] = f2tf32(av.w);
            unsigned* bs = &Bs[row * SST + lcol];
            bs[0] = f2tf32(bv.x); bs[1] = f2tf32(bv.y);
            bs[2] = f2tf32(bv.z); bs[3] = f2tf32(bv.w);
        }
        __syncthreads();

#pragma unroll
        for (int k8 = 0; k8 < 4; k8++) {
            int c = k8 * 8 + tg;
            unsigned afr[2][4], bfr[8][2];
#pragma unroll
            for (int mi = 0; mi < 2; mi++) {
                int r = wm * 32 + mi * 16 + g;
                afr[mi][0] = As[r * SST + c];
                afr[mi][1] = As[(r + 8) * SST + c];
                afr[mi][2] = As[r * SST + c + 4];
                afr[mi][3] = As[(r + 8) * SST + c + 4];
            }
#pragma unroll
            for (int ni = 0; ni < 8; ni++) {
                int n = wn * 64 + ni * 8 + g;
                bfr[ni][0] = Bs[n * SST + c];
                bfr[ni][1] = Bs[n * SST + c + 4];
            }
#pragma unroll
            for (int mi = 0; mi < 2; mi++)
#pragma unroll
                for (int ni = 0; ni < 8; ni++)
                    mma_tf32(acc[mi][ni], afr[mi], bfr[ni]);
        }
    }

#pragma unroll
    for (int mi = 0; mi < 2; mi++)
#pragma unroll
        for (int ni = 0; ni < 8; ni++) {
            int r0 = bm + wm * 32 + mi * 16 + g;
            int cc = bn + wn * 64 + ni * 8 + 2 * tg;
            *(float2*)&C[(size_t)r0 * DM + cc] =
                make_float2(acc[mi][ni][0], acc[mi][ni][1]);
            *(float2*)&C[(size_t)(r0 + 8) * DM + cc] =
                make_float2(acc[mi][ni][2], acc[mi][ni][3]);
        }
}

__global__ void __launch_bounds__(256) gemm_qkv_kernel(const float* __restrict__ x,
                                                       const float* __restrict__ Wq,
                                                       const float* __restrict__ Wk,
                                                       const float* __restrict__ Wv) {
    const float* B;
    float* C;
    if (blockIdx.z == 0)      { B = Wq; C = g_Q; }
    else if (blockIdx.z == 1) { B = Wk; C = g_K; }
    else                      { B = Wv; C = g_V; }
    gemm_body(C, x, B);
}

__global__ void __launch_bounds__(256) gemm_out_kernel(float* __restrict__ C,
                                                       const float* __restrict__ Wo) {
    gemm_body(C, g_att, Wo);
}

// ---------------------------------------------------------------------------
// Tensor-core flash attention.
// Block = (128-query tile, head). 8 warps; warp w owns query rows w*16..+15,
// so softmax row statistics live inside one warp (quad butterflies).
// Key tile = 64. S = QK^T via split tf32 (qh*kh + qh*kl + ql*kh: ~fp32
// accurate). Softmax with FMA-pipe exp2 (no MUFU). O += P*V with P single
// tf32 (only rounding introduced here) and V split.
// Smem strides: K arrays 68 (fragment bank = 4g+tg -> conflict-free),
// V arrays 72 (bank = 8tg+g -> conflict-free), P 68 (A-frag conflict-free).
// ---------------------------------------------------------------------------
#define BQ 128
#define BK 64
#define KST 68
#define VST 72

__global__ void __launch_bounds__(256) attn_tc_kernel(const int* __restrict__ mask) {
    extern __shared__ unsigned smu[];
    unsigned* KH = smu;                    // 64*68
    unsigned* KL = KH + BK * KST;          // 64*68
    unsigned* VH = KL + BK * KST;          // 64*72
    unsigned* VL = VH + BK * VST;          // 64*72
    float*    PS = (float*)(VL + BK * VST);// 128*68
    int*      MS = (int*)(PS + BQ * KST);  // 64

    int tid = threadIdx.x;
    int lane = tid & 31, w = tid >> 5;
    int g = lane >> 2, tg = lane & 3;
    int h = blockIdx.y;
    int q0 = blockIdx.x * BQ;

    // --- Q fragments (registers, split hi/lo), rows w*16+{g,g+8} ---
    unsigned qh[8][4], ql[8][4];
    {
        const float* Qg = g_Q + (size_t)(q0 + w * 16) * DM + h * HD;
#pragma unroll
        for (int ks = 0; ks < 8; ks++) {
            int c0 = ks * 8 + tg;
#pragma unroll
            for (int j = 0; j < 4; j++) {
                int r = (j & 1) ? g + 8 : g;
                int c = (j & 2) ? c0 + 4 : c0;
                float v = Qg[(size_t)r * DM + c];
                unsigned hi = f2tf32(v);
                qh[ks][j] = hi;
                ql[ks][j] = f2tf32(v - __uint_as_float(hi));
            }
        }
    }

    float o[8][4];
#pragma unroll
    for (int ni = 0; ni < 8; ni++)
#pragma unroll
        for (int j = 0; j < 4; j++) o[ni][j] = 0.0f;
    float mA = -3.0e38f, mB = -3.0e38f, lA = 0.0f, lB = 0.0f;

    for (int kt = 0; kt < SEQ / BK; kt++) {
        int k0 = kt * BK;
        __syncthreads();
        // --- cooperative load + split of K, V tiles ---
        {
            const float* Kg = g_K + (size_t)k0 * DM + h * HD;
            const float* Vg = g_V + (size_t)k0 * DM + h * HD;
            for (int slot = tid; slot < 1024; slot += 256) {
                int row = slot >> 4, c4 = (slot & 15) * 4;
                float4 kv = *(const float4*)&Kg[(size_t)row * DM + c4];
                float4 vv = *(const float4*)&Vg[(size_t)row * DM + c4];
                float kf[4] = {kv.x, kv.y, kv.z, kv.w};
                float vf[4] = {vv.x, vv.y, vv.z, vv.w};
#pragma unroll
                for (int j = 0; j < 4; j++) {
                    unsigned khb = f2tf32(kf[j]);
                    KH[row * KST + c4 + j] = khb;
                    KL[row * KST + c4 + j] = f2tf32(kf[j] - __uint_as_float(khb));
                    unsigned vhb = f2tf32(vf[j]);
                    VH[row * VST + c4 + j] = vhb;
                    VL[row * VST + c4 + j] = f2tf32(vf[j] - __uint_as_float(vhb));
                }
            }
            if (tid < 64) MS[tid] = mask[k0 + tid];
        }
        __syncthreads();

        // --- S = Q . K^T (split tf32) ---
        float sacc[8][4];
#pragma unroll
        for (int ni = 0; ni < 8; ni++)
#pragma unroll
            for (int j = 0; j < 4; j++) sacc[ni][j] = 0.0f;

#pragma unroll
        for (int ks = 0; ks < 8; ks++) {
#pragma unroll
            for (int ni = 0; ni < 8; ni++) {
                unsigned bh[2], bl[2];
                int kr = ni * 8 + g;
                bh[0] = KH[kr * KST + ks * 8 + tg];
                bh[1] = KH[kr * KST + ks * 8 + tg + 4];
                bl[0] = KL[kr * KST + ks * 8 + tg];
                bl[1] = KL[kr * KST + ks * 8 + tg + 4];
                mma_tf32(sacc[ni], qh[ks], bh);
                mma_tf32(sacc[ni], qh[ks], bl);
                mma_tf32(sacc[ni], ql[ks], bh);
            }
        }

        // --- scale + mask ---
#pragma unroll
        for (int ni = 0; ni < 8; ni++) {
            int m0 = MS[ni * 8 + 2 * tg];
            int m1 = MS[ni * 8 + 2 * tg + 1];
            sacc[ni][0] = m0 ? sacc[ni][0] * 0.125f : -1.0e9f;
            sacc[ni][1] = m1 ? sacc[ni][1] * 0.125f : -1.0e9f;
            sacc[ni][2] = m0 ? sacc[ni][2] * 0.125f : -1.0e9f;
            sacc[ni][3] = m1 ? sacc[ni][3] * 0.125f : -1.0e9f;
        }

        // --- online softmax (rows g and g+8 of this warp's 16) ---
        float mxA = -3.0e38f, mxB = -3.0e38f;
#pragma unroll
        for (int ni = 0; ni < 8; ni++) {
            mxA = fmaxf(mxA, fmaxf(sacc[ni][0], sacc[ni][1]));
            mxB = fmaxf(mxB, fmaxf(sacc[ni][2], sacc[ni][3]));
        }
        mxA = fmaxf(mxA, __shfl_xor_sync(0xffffffffu, mxA, 1));
        mxA = fmaxf(mxA, __shfl_xor_sync(0xffffffffu, mxA, 2));
        mxB = fmaxf(mxB, __shfl_xor_sync(0xffffffffu, mxB, 1));
        mxB = fmaxf(mxB, __shfl_xor_sync(0xffffffffu, mxB, 2));

        float mnA = fmaxf(mA, mxA), mnB = fmaxf(mB, mxB);
        float corrA = exp2p((mA - mnA) * LOG2E);
        float corrB = exp2p((mB - mnB) * LOG2E);

        float sumA = 0.0f, sumB = 0.0f;
        int rowA = w * 16 + g, rowB = rowA + 8;
#pragma unroll
        for (int ni = 0; ni < 8; ni++) {
            float p0 = exp2p((sacc[ni][0] - mnA) * LOG2E);
            float p1 = exp2p((sacc[ni][1] - mnA) * LOG2E);
            float p2 = exp2p((sacc[ni][2] - mnB) * LOG2E);
            float p3 = exp2p((sacc[ni][3] - mnB) * LOG2E);
            sumA += p0 + p1;
            sumB += p2 + p3;
            *(float2*)&PS[rowA * KST + ni * 8 + 2 * tg] = make_float2(p0, p1);
            *(float2*)&PS[rowB * KST + ni * 8 + 2 * tg] = make_float2(p2, p3);
        }
        sumA += __shfl_xor_sync(0xffffffffu, sumA, 1);
        sumA += __shfl_xor_sync(0xffffffffu, sumA, 2);
        sumB += __shfl_xor_sync(0xffffffffu, sumB, 1);
        sumB += __shfl_xor_sync(0xffffffffu, sumB, 2);

        lA = lA * corrA + sumA;
        lB = lB * corrB + sumB;
        mA = mnA;
        mB = mnB;
#pragma unroll
        for (int ni = 0; ni < 8; ni++) {
            o[ni][0] *= corrA; o[ni][1] *= corrA;
            o[ni][2] *= corrB; o[ni][3] *= corrB;
        }
        __syncwarp();

        // --- O += P . V (P single tf32, V split) ---
#pragma unroll
        for (int ks = 0; ks < 8; ks++) {
            unsigned pa[4];
            pa[0] = f2tf32(PS[rowA * KST + ks * 8 + tg]);
            pa[1] = f2tf32(PS[rowB * KST + ks * 8 + tg]);
            pa[2] = f2tf32(PS[rowA * KST + ks * 8 + tg + 4]);
            pa[3] = f2tf32(PS[rowB * KST + ks * 8 + tg + 4]);
#pragma unroll
            for (int ni = 0; ni < 8; ni++) {
                unsigned bh[2], bl[2];
                bh[0] = VH[(ks * 8 + tg) * VST + ni * 8 + g];
                bh[1] = VH[(ks * 8 + tg + 4) * VST + ni * 8 + g];
                bl[0] = VL[(ks * 8 + tg) * VST + ni * 8 + g];
                bl[1] = VL[(ks * 8 + tg + 4) * VST + ni * 8 + g];
                mma_tf32(o[ni], pa, bh);
                mma_tf32(o[ni], pa, bl);
            }
        }
    }

    // --- normalize + store ---
    float invA = 1.0f / lA, invB = 1.0f / lB;
    float* Og = g_att + (size_t)(q0 + w * 16) * DM + h * HD;
#pragma unroll
    for (int ni = 0; ni < 8; ni++) {
        *(float2*)&Og[(size_t)g * DM + ni * 8 + 2 * tg] =
            make_float2(o[ni][0] * invA, o[ni][1] * invA);
        *(float2*)&Og[(size_t)(g + 8) * DM + ni * 8 + 2 * tg] =
            make_float2(o[ni][2] * invB, o[ni][3] * invB);
    }
}

// ---------------------------------------------------------------------------
// launch
// ---------------------------------------------------------------------------
extern "C" void kernel_launch(void* const* d_in, const int* in_sizes, int n_in,
                              void* d_out, int out_size) {
    const float* x    = (const float*)d_in[0];
    const int*   mask = (const int*)d_in[1];
    const float* Wq   = (const float*)d_in[2];
    const float* Wk   = (const float*)d_in[3];
    const float* Wv   = (const float*)d_in[4];
    const float* Wo   = (const float*)d_in[5];
    float* out = (float*)d_out;

    gemm_qkv_kernel<<<dim3(16, 16, 3), 256>>>(x, Wq, Wk, Wv);

    rope_table_kernel<<<(SEQ * 32 + 255) / 256, 256>>>();
    rope_apply_kernel<<<dim3((SEQ * NH + 255) / 256, 2), 256>>>();

    const int attn_smem =
        (2 * BK * KST + 2 * BK * VST + BQ * KST + BK) * (int)sizeof(unsigned);
    cudaFuncSetAttribute(attn_tc_kernel, cudaFuncAttributeMaxDynamicSharedMemorySize,
                         attn_smem);
    attn_tc_kernel<<<dim3(SEQ / BQ, NH), 256, attn_smem>>>(mask);

    gemm_out_kernel<<<dim3(16, 16), 256>>>(out, Wo);
}

// round 4
// speedup vs baseline: 2.3403x; 1.2062x over previous
#include <cuda_runtime.h>

#define SEQ 2048
#define DM 2048
#define NH 32
#define HD 64

// Scratch (static device allocations are allowed; cudaMalloc is not)
__device__ float g_Q[SEQ * DM];
__device__ float g_K[SEQ * DM];
__device__ float g_V[SEQ * DM];
__device__ float g_att[SEQ * DM];
__device__ float g_cos[SEQ * 32];
__device__ float g_sin[SEQ * 32];

// ---------------------------------------------------------------------------
// tf32 helpers
// ---------------------------------------------------------------------------
__device__ __forceinline__ unsigned f2tf32(float f) {
    unsigned r;
    asm("cvt.rna.tf32.f32 %0, %1;" : "=r"(r) : "f"(f));
    return r;
}

__device__ __forceinline__ void mma_tf32(float* c, const unsigned* a, const unsigned* b) {
    asm volatile(
        "mma.sync.aligned.m16n8k8.row.col.f32.tf32.tf32.f32 "
        "{%0,%1,%2,%3}, {%4,%5,%6,%7}, {%8,%9}, {%0,%1,%2,%3};"
        : "+f"(c[0]), "+f"(c[1]), "+f"(c[2]), "+f"(c[3])
        : "r"(a[0]), "r"(a[1]), "r"(a[2]), "r"(a[3]), "r"(b[0]), "r"(b[1]));
}

// FMA-pipe exp2 (no MUFU): 2^y, y clamped at -126. ~1.5e-6 rel error.
__device__ __forceinline__ float exp2p(float y) {
    y = fmaxf(y, -126.0f);
    float z = y + 12582912.0f;                 // round-to-nearest int
    int i = __float_as_int(z) - 0x4B400000;
    float f = y - (z - 12582912.0f);           // f in [-0.5, 0.5]
    float p = 1.3534384e-3f;
    p = fmaf(p, f, 9.6181291e-3f);
    p = fmaf(p, f, 5.5504109e-2f);
    p = fmaf(p, f, 2.4022650e-1f);
    p = fmaf(p, f, 6.9314718e-1f);
    p = fmaf(p, f, 1.0f);
    return __int_as_float(__float_as_int(p) + (i << 23));
}

#define LOG2E 1.4426950408889634f

// ---------------------------------------------------------------------------
// RoPE cos/sin table
// ---------------------------------------------------------------------------
__global__ void rope_table_kernel() {
    int idx = blockIdx.x * blockDim.x + threadIdx.x;
    if (idx >= SEQ * 32) return;
    int l = idx >> 5;
    int j = idx & 31;
    float invf = powf(10000.0f, -(float)j * (1.0f / 32.0f));
    float fr = (float)l * invf;
    g_cos[idx] = cosf(fr);
    g_sin[idx] = sinf(fr);
}

// ---------------------------------------------------------------------------
// RoPE apply (concatenated-halves layout)
// ---------------------------------------------------------------------------
__global__ void __launch_bounds__(256) rope_apply_kernel() {
    int t = blockIdx.x * blockDim.x + threadIdx.x;
    if (t >= SEQ * NH) return;
    int l = t >> 5;
    int h = t & 31;
    float* base = (blockIdx.y == 0 ? g_Q : g_K) + (size_t)l * DM + h * HD;

    float v[64];
#pragma unroll
    for (int i = 0; i < 16; i++)
        *(float4*)(v + 4 * i) = *(const float4*)(base + 4 * i);

#pragma unroll
    for (int j = 0; j < 32; j++) {
        float c = g_cos[l * 32 + j];
        float s = g_sin[l * 32 + j];
        float x1 = v[2 * j];
        float x2 = v[2 * j + 1];
        v[2 * j]     = x1 * c - x2 * s;
        v[2 * j + 1] = x1 * s + x2 * c;
    }
#pragma unroll
    for (int j = 0; j < 32; j++) {
        base[j]      = v[2 * j];
        base[32 + j] = v[2 * j + 1];
    }
}

// ---------------------------------------------------------------------------
// TF32 tensor-core GEMM with register-prefetch pipeline, 2 CTAs/SM.
// C[M,N] = A[M,K] * B[N,K]^T, M=N=K=2048. 128x128x32 tile, 8 warps 4x2.
// ---------------------------------------------------------------------------
#define SST 36

__device__ __forceinline__ void gemm_body(float* __restrict__ C,
                                          const float* __restrict__ A,
                                          const float* __restrict__ B) {
    __shared__ unsigned As[128 * SST];
    __shared__ unsigned Bs[128 * SST];

    int tid = threadIdx.x;
    int lane = tid & 31, warp = tid >> 5;
    int wm = warp >> 1, wn = warp & 1;
    int g = lane >> 2, tg = lane & 3;
    int bm = blockIdx.y * 128, bn = blockIdx.x * 128;

    int lrow = tid >> 3;
    int lcol = (tid & 7) * 4;

    float acc[2][8][4];
#pragma unroll
    for (int mi = 0; mi < 2; mi++)
#pragma unroll
        for (int ni = 0; ni < 8; ni++)
#pragma unroll
            for (int j = 0; j < 4; j++) acc[mi][ni][j] = 0.0f;

    const float* Ap = A + (size_t)(bm + lrow) * DM + lcol;
    const float* Bp = B + (size_t)(bn + lrow) * DM + lcol;

    float4 av[4], bv[4];
#pragma unroll
    for (int p = 0; p < 4; p++) {
        av[p] = *(const float4*)(Ap + (size_t)p * 32 * DM);
        bv[p] = *(const float4*)(Bp + (size_t)p * 32 * DM);
    }

    for (int k0 = 0; k0 < DM; k0 += 32) {
        __syncthreads();
#pragma unroll
        for (int p = 0; p < 4; p++) {
            int row = lrow + p * 32;
            unsigned* as = &As[row * SST + lcol];
            as[0] = f2tf32(av[p].x); as[1] = f2tf32(av[p].y);
            as[2] = f2tf32(av[p].z); as[3] = f2tf32(av[p].w);
            unsigned* bs = &Bs[row * SST + lcol];
            bs[0] = f2tf32(bv[p].x); bs[1] = f2tf32(bv[p].y);
            bs[2] = f2tf32(bv[p].z); bs[3] = f2tf32(bv[p].w);
        }
        __syncthreads();

        if (k0 + 32 < DM) {
#pragma unroll
            for (int p = 0; p < 4; p++) {
                av[p] = *(const float4*)(Ap + (size_t)p * 32 * DM + k0 + 32);
                bv[p] = *(const float4*)(Bp + (size_t)p * 32 * DM + k0 + 32);
            }
        }

#pragma unroll
        for (int k8 = 0; k8 < 4; k8++) {
            int c = k8 * 8 + tg;
            unsigned afr[2][4], bfr[8][2];
#pragma unroll
            for (int mi = 0; mi < 2; mi++) {
                int r = wm * 32 + mi * 16 + g;
                afr[mi][0] = As[r * SST + c];
                afr[mi][1] = As[(r + 8) * SST + c];
                afr[mi][2] = As[r * SST + c + 4];
                afr[mi][3] = As[(r + 8) * SST + c + 4];
            }
#pragma unroll
            for (int ni = 0; ni < 8; ni++) {
                int n = wn * 64 + ni * 8 + g;
                bfr[ni][0] = Bs[n * SST + c];
                bfr[ni][1] = Bs[n * SST + c + 4];
            }
#pragma unroll
            for (int mi = 0; mi < 2; mi++)
#pragma unroll
                for (int ni = 0; ni < 8; ni++)
                    mma_tf32(acc[mi][ni], afr[mi], bfr[ni]);
        }
    }

#pragma unroll
    for (int mi = 0; mi < 2; mi++)
#pragma unroll
        for (int ni = 0; ni < 8; ni++) {
            int r0 = bm + wm * 32 + mi * 16 + g;
            int cc = bn + wn * 64 + ni * 8 + 2 * tg;
            *(float2*)&C[(size_t)r0 * DM + cc] =
                make_float2(acc[mi][ni][0], acc[mi][ni][1]);
            *(float2*)&C[(size_t)(r0 + 8) * DM + cc] =
                make_float2(acc[mi][ni][2], acc[mi][ni][3]);
        }
}

__global__ void __launch_bounds__(256, 2) gemm_qkv_kernel(const float* __restrict__ x,
                                                          const float* __restrict__ Wq,
                                                          const float* __restrict__ Wk,
                                                          const float* __restrict__ Wv) {
    const float* B;
    float* C;
    if (blockIdx.z == 0)      { B = Wq; C = g_Q; }
    else if (blockIdx.z == 1) { B = Wk; C = g_K; }
    else                      { B = Wv; C = g_V; }
    gemm_body(C, x, B);
}

__global__ void __launch_bounds__(256, 2) gemm_out_kernel(float* __restrict__ C,
                                                          const float* __restrict__ Wo) {
    gemm_body(C, g_att, Wo);
}

// ---------------------------------------------------------------------------
// Tensor-core flash attention, v2.
// Block = (128-query tile, head); 8 warps, warp w owns rows w*16..+15.
// Changes vs round 3:
//  - P never goes to smem: the S C-fragment is permuted into the PV
//    A-fragment with quad-local shuffles.
//  - Q-lo operand lives in smem (frees 32 regs) -> regs<=128, 2 CTAs/SM.
// Numerics identical: S = qh*kh + qh*kl + ql*kh, P single tf32, V split.
// ---------------------------------------------------------------------------
#define BQ 128
#define BK 64
#define KST 68
#define VST 72

// smem word offsets
#define OFF_KH 0
#define OFF_KL (OFF_KH + BK * KST)        // 4352
#define OFF_VH (OFF_KL + BK * KST)        // 8704
#define OFF_VL (OFF_VH + BK * VST)        // 13312
#define OFF_QL (OFF_VL + BK * VST)        // 17920
#define OFF_MS (OFF_QL + BQ * KST)        // 26624
#define SMEM_WORDS (OFF_MS + BK)          // 26688

__global__ void __launch_bounds__(256, 2) attn_tc_kernel(const int* __restrict__ mask) {
    extern __shared__ unsigned smu[];
    unsigned* KH = smu + OFF_KH;
    unsigned* KL = smu + OFF_KL;
    unsigned* VH = smu + OFF_VH;
    unsigned* VL = smu + OFF_VL;
    unsigned* QL = smu + OFF_QL;
    int*      MS = (int*)(smu + OFF_MS);

    int tid = threadIdx.x;
    int lane = tid & 31, w = tid >> 5;
    int g = lane >> 2, tg = lane & 3;
    int h = blockIdx.y;
    int q0 = blockIdx.x * BQ;

    // --- cooperative Q load + split. Q-hi staged in KH/KL (contiguous
    //     128*68 words), Q-lo stays in QL. Then per-warp hi frags -> regs. ---
    {
        const float* Qg = g_Q + (size_t)q0 * DM + h * HD;
        unsigned* QH = KH;  // temporary overlay
        for (int slot = tid; slot < 2048; slot += 256) {
            int row = slot >> 4, c4 = (slot & 15) * 4;
            float4 qv = *(const float4*)&Qg[(size_t)row * DM + c4];
            float qf[4] = {qv.x, qv.y, qv.z, qv.w};
#pragma unroll
            for (int j = 0; j < 4; j++) {
                unsigned hi = f2tf32(qf[j]);
                QH[row * KST + c4 + j] = hi;
                QL[row * KST + c4 + j] = f2tf32(qf[j] - __uint_as_float(hi));
            }
        }
    }
    __syncthreads();

    unsigned qh[8][4];
    {
        const unsigned* QH = KH;
        int rA = w * 16 + g, rB = rA + 8;
#pragma unroll
        for (int ks = 0; ks < 8; ks++) {
            int c = ks * 8 + tg;
            qh[ks][0] = QH[rA * KST + c];
            qh[ks][1] = QH[rB * KST + c];
            qh[ks][2] = QH[rA * KST + c + 4];
            qh[ks][3] = QH[rB * KST + c + 4];
        }
    }

    float o[8][4];
#pragma unroll
    for (int ni = 0; ni < 8; ni++)
#pragma unroll
        for (int j = 0; j < 4; j++) o[ni][j] = 0.0f;
    float mA = -3.0e38f, mB = -3.0e38f, lA = 0.0f, lB = 0.0f;

    int rowQA = w * 16 + g;  // for QL reads
    int sh0 = (lane & ~3) | (tg >> 1);   // src lane for cols tg
    int sh1 = sh0 + 2;                   // src lane for cols tg+4
    bool odd = (tg & 1);

    for (int kt = 0; kt < SEQ / BK; kt++) {
        int k0 = kt * BK;
        __syncthreads();  // protect K/V/(QH overlay on first iter) readers
        {
            const float* Kg = g_K + (size_t)k0 * DM + h * HD;
            const float* Vg = g_V + (size_t)k0 * DM + h * HD;
            for (int slot = tid; slot < 1024; slot += 256) {
                int row = slot >> 4, c4 = (slot & 15) * 4;
                float4 kv = *(const float4*)&Kg[(size_t)row * DM + c4];
                float4 vv = *(const float4*)&Vg[(size_t)row * DM + c4];
                float kf[4] = {kv.x, kv.y, kv.z, kv.w};
                float vf[4] = {vv.x, vv.y, vv.z, vv.w};
#pragma unroll
                for (int j = 0; j < 4; j++) {
                    unsigned khb = f2tf32(kf[j]);
                    KH[row * KST + c4 + j] = khb;
                    KL[row * KST + c4 + j] = f2tf32(kf[j] - __uint_as_float(khb));
                    unsigned vhb = f2tf32(vf[j]);
                    VH[row * VST + c4 + j] = vhb;
                    VL[row * VST + c4 + j] = f2tf32(vf[j] - __uint_as_float(vhb));
                }
            }
            if (tid < 64) MS[tid] = mask[k0 + tid];
        }
        __syncthreads();

        // --- S = Q . K^T (split tf32) ---
        float sacc[8][4];
#pragma unroll
        for (int ni = 0; ni < 8; ni++)
#pragma unroll
            for (int j = 0; j < 4; j++) sacc[ni][j] = 0.0f;

#pragma unroll
        for (int ks = 0; ks < 8; ks++) {
            unsigned ql[4];
            {
                int c = ks * 8 + tg;
                ql[0] = QL[rowQA * KST + c];
                ql[1] = QL[(rowQA + 8) * KST + c];
                ql[2] = QL[rowQA * KST + c + 4];
                ql[3] = QL[(rowQA + 8) * KST + c + 4];
            }
#pragma unroll
            for (int ni = 0; ni < 8; ni++) {
                unsigned bh[2], bl[2];
                int kr = ni * 8 + g;
                bh[0] = KH[kr * KST + ks * 8 + tg];
                bh[1] = KH[kr * KST + ks * 8 + tg + 4];
                bl[0] = KL[kr * KST + ks * 8 + tg];
                bl[1] = KL[kr * KST + ks * 8 + tg + 4];
                mma_tf32(sacc[ni], qh[ks], bh);
                mma_tf32(sacc[ni], qh[ks], bl);
                mma_tf32(sacc[ni], ql, bh);
            }
        }

        // --- scale + mask ---
#pragma unroll
        for (int ni = 0; ni < 8; ni++) {
            int m0 = MS[ni * 8 + 2 * tg];
            int m1 = MS[ni * 8 + 2 * tg + 1];
            sacc[ni][0] = m0 ? sacc[ni][0] * 0.125f : -1.0e9f;
            sacc[ni][1] = m1 ? sacc[ni][1] * 0.125f : -1.0e9f;
            sacc[ni][2] = m0 ? sacc[ni][2] * 0.125f : -1.0e9f;
            sacc[ni][3] = m1 ? sacc[ni][3] * 0.125f : -1.0e9f;
        }

        // --- online softmax (rows g, g+8 of this warp) ---
        float mxA = -3.0e38f, mxB = -3.0e38f;
#pragma unroll
        for (int ni = 0; ni < 8; ni++) {
            mxA = fmaxf(mxA, fmaxf(sacc[ni][0], sacc[ni][1]));
            mxB = fmaxf(mxB, fmaxf(sacc[ni][2], sacc[ni][3]));
        }
        mxA = fmaxf(mxA, __shfl_xor_sync(0xffffffffu, mxA, 1));
        mxA = fmaxf(mxA, __shfl_xor_sync(0xffffffffu, mxA, 2));
        mxB = fmaxf(mxB, __shfl_xor_sync(0xffffffffu, mxB, 1));
        mxB = fmaxf(mxB, __shfl_xor_sync(0xffffffffu, mxB, 2));

        float mnA = fmaxf(mA, mxA), mnB = fmaxf(mB, mxB);
        float corrA = exp2p((mA - mnA) * LOG2E);
        float corrB = exp2p((mB - mnB) * LOG2E);

        float sumA = 0.0f, sumB = 0.0f;
#pragma unroll
        for (int ni = 0; ni < 8; ni++) {
            sacc[ni][0] = exp2p((sacc[ni][0] - mnA) * LOG2E);
            sacc[ni][1] = exp2p((sacc[ni][1] - mnA) * LOG2E);
            sacc[ni][2] = exp2p((sacc[ni][2] - mnB) * LOG2E);
            sacc[ni][3] = exp2p((sacc[ni][3] - mnB) * LOG2E);
            sumA += sacc[ni][0] + sacc[ni][1];
            sumB += sacc[ni][2] + sacc[ni][3];
        }
        sumA += __shfl_xor_sync(0xffffffffu, sumA, 1);
        sumA += __shfl_xor_sync(0xffffffffu, sumA, 2);
        sumB += __shfl_xor_sync(0xffffffffu, sumB, 1);
        sumB += __shfl_xor_sync(0xffffffffu, sumB, 2);

        lA = lA * corrA + sumA;
        lB = lB * corrB + sumB;
        mA = mnA;
        mB = mnB;
#pragma unroll
        for (int ni = 0; ni < 8; ni++) {
            o[ni][0] *= corrA; o[ni][1] *= corrA;
            o[ni][2] *= corrB; o[ni][3] *= corrB;
        }

        // --- O += P . V : P via quad-local shuffle of sacc (no smem) ---
#pragma unroll
        for (int ks = 0; ks < 8; ks++) {
            float e0 = __shfl_sync(0xffffffffu, sacc[ks][0], sh0);
            float e1 = __shfl_sync(0xffffffffu, sacc[ks][1], sh0);
            float e2 = __shfl_sync(0xffffffffu, sacc[ks][2], sh0);
            float e3 = __shfl_sync(0xffffffffu, sacc[ks][3], sh0);
            float f0 = __shfl_sync(0xffffffffu, sacc[ks][0], sh1);
            float f1 = __shfl_sync(0xffffffffu, sacc[ks][1], sh1);
            float f2 = __shfl_sync(0xffffffffu, sacc[ks][2], sh1);
            float f3 = __shfl_sync(0xffffffffu, sacc[ks][3], sh1);
            unsigned pa[4];
            pa[0] = f2tf32(odd ? e1 : e0);
            pa[1] = f2tf32(odd ? e3 : e2);
            pa[2] = f2tf32(odd ? f1 : f0);
            pa[3] = f2tf32(odd ? f3 : f2);
#pragma unroll
            for (int ni = 0; ni < 8; ni++) {
                unsigned bh[2], bl[2];
                bh[0] = VH[(ks * 8 + tg) * VST + ni * 8 + g];
                bh[1] = VH[(ks * 8 + tg + 4) * VST + ni * 8 + g];
                bl[0] = VL[(ks * 8 + tg) * VST + ni * 8 + g];
                bl[1] = VL[(ks * 8 + tg + 4) * VST + ni * 8 + g];
                mma_tf32(o[ni], pa, bh);
                mma_tf32(o[ni], pa, bl);
            }
        }
    }

    // --- normalize + store ---
    float invA = 1.0f / lA, invB = 1.0f / lB;
    float* Og = g_att + (size_t)(q0 + w * 16) * DM + h * HD;
#pragma unroll
    for (int ni = 0; ni < 8; ni++) {
        *(float2*)&Og[(size_t)g * DM + ni * 8 + 2 * tg] =
            make_float2(o[ni][0] * invA, o[ni][1] * invA);
        *(float2*)&Og[(size_t)(g + 8) * DM + ni * 8 + 2 * tg] =
            make_float2(o[ni][2] * invB, o[ni][3] * invB);
    }
}

// ---------------------------------------------------------------------------
// launch
// ---------------------------------------------------------------------------
extern "C" void kernel_launch(void* const* d_in, const int* in_sizes, int n_in,
                              void* d_out, int out_size) {
    const float* x    = (const float*)d_in[0];
    const int*   mask = (const int*)d_in[1];
    const float* Wq   = (const float*)d_in[2];
    const float* Wk   = (const float*)d_in[3];
    const float* Wv   = (const float*)d_in[4];
    const float* Wo   = (const float*)d_in[5];
    float* out = (float*)d_out;

    gemm_qkv_kernel<<<dim3(16, 16, 3), 256>>>(x, Wq, Wk, Wv);

    rope_table_kernel<<<(SEQ * 32 + 255) / 256, 256>>>();
    rope_apply_kernel<<<dim3((SEQ * NH + 255) / 256, 2), 256>>>();

    const int attn_smem = SMEM_WORDS * (int)sizeof(unsigned);  // 106752
    cudaFuncSetAttribute(attn_tc_kernel, cudaFuncAttributeMaxDynamicSharedMemorySize,
                         attn_smem);
    attn_tc_kernel<<<dim3(SEQ / BQ, NH), 256, attn_smem>>>(mask);

    gemm_out_kernel<<<dim3(16, 16), 256>>>(out, Wo);
}

// round 6
// speedup vs baseline: 3.0103x; 1.2863x over previous
#include <cuda_runtime.h>
#include <cuda_bf16.h>

#define SEQ 2048
#define DM 2048
#define NH 32
#define HD 64

// Scratch (static device allocations are allowed; cudaMalloc is not)
__device__ float g_Q[SEQ * DM];
__device__ float g_K[SEQ * DM];
__device__ float g_V[SEQ * DM];
__device__ float g_att[SEQ * DM];
__device__ float g_cos[SEQ * 32];
__device__ float g_sin[SEQ * 32];

// ---------------------------------------------------------------------------
// tf32 helpers (GEMMs)
// ---------------------------------------------------------------------------
__device__ __forceinline__ unsigned f2tf32(float f) {
    unsigned r;
    asm("cvt.rna.tf32.f32 %0, %1;" : "=r"(r) : "f"(f));
    return r;
}

__device__ __forceinline__ void mma_tf32(float* c, const unsigned* a, const unsigned* b) {
    asm volatile(
        "mma.sync.aligned.m16n8k8.row.col.f32.tf32.tf32.f32 "
        "{%0,%1,%2,%3}, {%4,%5,%6,%7}, {%8,%9}, {%0,%1,%2,%3};"
        : "+f"(c[0]), "+f"(c[1]), "+f"(c[2]), "+f"(c[3])
        : "r"(a[0]), "r"(a[1]), "r"(a[2]), "r"(a[3]), "r"(b[0]), "r"(b[1]));
}

// ---------------------------------------------------------------------------
// bf16 helpers (attention)
// ---------------------------------------------------------------------------
__device__ __forceinline__ void mma_bf16(float* c, const unsigned* a, const unsigned* b) {
    asm volatile(
        "mma.sync.aligned.m16n8k16.row.col.f32.bf16.bf16.f32 "
        "{%0,%1,%2,%3}, {%4,%5,%6,%7}, {%8,%9}, {%0,%1,%2,%3};"
        : "+f"(c[0]), "+f"(c[1]), "+f"(c[2]), "+f"(c[3])
        : "r"(a[0]), "r"(a[1]), "r"(a[2]), "r"(a[3]), "r"(b[0]), "r"(b[1]));
}

// word with low half = bf16(e0), high half = bf16(e1)
__device__ __forceinline__ unsigned pack_bf(float e0, float e1) {
    unsigned r;
    asm("cvt.rn.bf16x2.f32 %0, %1, %2;" : "=r"(r) : "f"(e1), "f"(e0));
    return r;
}

__device__ __forceinline__ float bf_hi(float x) {
    return __bfloat162float(__float2bfloat16(x));
}

// FMA-pipe exp2 (no MUFU)
__device__ __forceinline__ float exp2p(float y) {
    y = fmaxf(y, -126.0f);
    float z = y + 12582912.0f;
    int i = __float_as_int(z) - 0x4B400000;
    float f = y - (z - 12582912.0f);
    float p = 1.3534384e-3f;
    p = fmaf(p, f, 9.6181291e-3f);
    p = fmaf(p, f, 5.5504109e-2f);
    p = fmaf(p, f, 2.4022650e-1f);
    p = fmaf(p, f, 6.9314718e-1f);
    p = fmaf(p, f, 1.0f);
    return __int_as_float(__float_as_int(p) + (i << 23));
}

#define LOG2E 1.4426950408889634f

// ---------------------------------------------------------------------------
// RoPE cos/sin table
// ---------------------------------------------------------------------------
__global__ void rope_table_kernel() {
    int idx = blockIdx.x * blockDim.x + threadIdx.x;
    if (idx >= SEQ * 32) return;
    int l = idx >> 5;
    int j = idx & 31;
    float invf = powf(10000.0f, -(float)j * (1.0f / 32.0f));
    float fr = (float)l * invf;
    g_cos[idx] = cosf(fr);
    g_sin[idx] = sinf(fr);
}

// ---------------------------------------------------------------------------
// TF32 tensor-core GEMM with register-prefetch, 2 CTAs/SM.
// C[M,N] = A[M,K] * B[N,K]^T, M=N=K=2048. 128x128x32 tile, 8 warps 4x2.
// ---------------------------------------------------------------------------
#define SST 36

__device__ __forceinline__ void gemm_body(float* __restrict__ C,
                                          const float* __restrict__ A,
                                          const float* __restrict__ B) {
    __shared__ unsigned As[128 * SST];
    __shared__ unsigned Bs[128 * SST];

    int tid = threadIdx.x;
    int lane = tid & 31, warp = tid >> 5;
    int wm = warp >> 1, wn = warp & 1;
    int g = lane >> 2, tg = lane & 3;
    int bm = blockIdx.y * 128, bn = blockIdx.x * 128;

    int lrow = tid >> 3;
    int lcol = (tid & 7) * 4;

    float acc[2][8][4];
#pragma unroll
    for (int mi = 0; mi < 2; mi++)
#pragma unroll
        for (int ni = 0; ni < 8; ni++)
#pragma unroll
            for (int j = 0; j < 4; j++) acc[mi][ni][j] = 0.0f;

    const float* Ap = A + (size_t)(bm + lrow) * DM + lcol;
    const float* Bp = B + (size_t)(bn + lrow) * DM + lcol;

    float4 av[4], bv[4];
#pragma unroll
    for (int p = 0; p < 4; p++) {
        av[p] = *(const float4*)(Ap + (size_t)p * 32 * DM);
        bv[p] = *(const float4*)(Bp + (size_t)p * 32 * DM);
    }

    for (int k0 = 0; k0 < DM; k0 += 32) {
        __syncthreads();
#pragma unroll
        for (int p = 0; p < 4; p++) {
            int row = lrow + p * 32;
            unsigned* as = &As[row * SST + lcol];
            as[0] = f2tf32(av[p].x); as[1] = f2tf32(av[p].y);
            as[2] = f2tf32(av[p].z); as[3] = f2tf32(av[p].w);
            unsigned* bs = &Bs[row * SST + lcol];
            bs[0] = f2tf32(bv[p].x); bs[1] = f2tf32(bv[p].y);
            bs[2] = f2tf32(bv[p].z); bs[3] = f2tf32(bv[p].w);
        }
        __syncthreads();

        if (k0 + 32 < DM) {
#pragma unroll
            for (int p = 0; p < 4; p++) {
                av[p] = *(const float4*)(Ap + (size_t)p * 32 * DM + k0 + 32);
                bv[p] = *(const float4*)(Bp + (size_t)p * 32 * DM + k0 + 32);
            }
        }

#pragma unroll
        for (int k8 = 0; k8 < 4; k8++) {
            int c = k8 * 8 + tg;
            unsigned afr[2][4], bfr[8][2];
#pragma unroll
            for (int mi = 0; mi < 2; mi++) {
                int r = wm * 32 + mi * 16 + g;
                afr[mi][0] = As[r * SST + c];
                afr[mi][1] = As[(r + 8) * SST + c];
                afr[mi][2] = As[r * SST + c + 4];
                afr[mi][3] = As[(r + 8) * SST + c + 4];
            }
#pragma unroll
            for (int ni = 0; ni < 8; ni++) {
                int n = wn * 64 + ni * 8 + g;
                bfr[ni][0] = Bs[n * SST + c];
                bfr[ni][1] = Bs[n * SST + c + 4];
            }
#pragma unroll
            for (int mi = 0; mi < 2; mi++)
#pragma unroll
                for (int ni = 0; ni < 8; ni++)
                    mma_tf32(acc[mi][ni], afr[mi], bfr[ni]);
        }
    }

#pragma unroll
    for (int mi = 0; mi < 2; mi++)
#pragma unroll
        for (int ni = 0; ni < 8; ni++) {
            int r0 = bm + wm * 32 + mi * 16 + g;
            int cc = bn + wn * 64 + ni * 8 + 2 * tg;
            *(float2*)&C[(size_t)r0 * DM + cc] =
                make_float2(acc[mi][ni][0], acc[mi][ni][1]);
            *(float2*)&C[(size_t)(r0 + 8) * DM + cc] =
                make_float2(acc[mi][ni][2], acc[mi][ni][3]);
        }
}

__global__ void __launch_bounds__(256, 2) gemm_qkv_kernel(const float* __restrict__ x,
                                                          const float* __restrict__ Wq,
                                                          const float* __restrict__ Wk,
                                                          const float* __restrict__ Wv) {
    const float* B;
    float* C;
    if (blockIdx.z == 0)      { B = Wq; C = g_Q; }
    else if (blockIdx.z == 1) { B = Wk; C = g_K; }
    else                      { B = Wv; C = g_V; }
    gemm_body(C, x, B);
}

__global__ void __launch_bounds__(256, 2) gemm_out_kernel(float* __restrict__ C,
                                                          const float* __restrict__ Wo) {
    gemm_body(C, g_att, Wo);
}

// ---------------------------------------------------------------------------
// Split-BF16 flash attention with fused RoPE.
// Block = (128-query tile, head); 8 warps, warp w owns rows w*16..+15.
// S = qh*kh + ql*kh + qh*kl (bf16 m16n8k16, fp32 accum): ~2^-17 accurate.
// PV likewise with P split in registers; the S C-fragment IS the PV
// A-fragment (no shuffles). RoPE applied during Q/K tile load (table).
// Smem: K/Q tiles [row][dimword] stride 36 (frag banks 4g+tg, clean);
// V transposed [keypair][dim] stride 72 (frag banks 8tg+g clean;
// uint4 stores conflict-free). 37 KB static -> 2 CTAs/SM.
// ---------------------------------------------------------------------------
#define BQ 128
#define BK 64
#define KWST 36
#define VWST 72

#define AOFF_KH 0                     // 64*36 = 2304
#define AOFF_KL 2304
#define AOFF_VH 4608                  // 32*72 = 2304
#define AOFF_VL 6912
#define AOFF_MS 9216
#define ASMEM_WORDS 9280              // 37120 B

__global__ void __launch_bounds__(256, 2) attn_bf16_kernel(const int* __restrict__ mask) {
    __shared__ unsigned smu[ASMEM_WORDS];
    unsigned* KH = smu + AOFF_KH;
    unsigned* KL = smu + AOFF_KL;
    unsigned* VH = smu + AOFF_VH;
    unsigned* VL = smu + AOFF_VL;
    int*      MS = (int*)(smu + AOFF_MS);

    int tid = threadIdx.x;
    int lane = tid & 31, w = tid >> 5;
    int g = lane >> 2, tg = lane & 3;
    int h = blockIdx.y;
    int q0 = blockIdx.x * BQ;

    // --- stage Q (rope + split) into smem overlay: QH on KH..KL, QL on VH..VL ---
    {
        unsigned* QH = smu + AOFF_KH;   // 128*36 = 4608 words
        unsigned* QL = smu + AOFF_VH;   // 128*36 = 4608 words
        const float* Qg = g_Q + (size_t)q0 * DM + h * HD;
        for (int slot = tid; slot < 2048; slot += 256) {
            int row = slot >> 4, j = slot & 15;
            int l = q0 + row;
            float4 q4 = *(const float4*)&Qg[(size_t)row * DM + 4 * j];
            float2 cs0 = *(const float2*)&g_cos[l * 32 + 2 * j];
            float2 sn0 = *(const float2*)&g_sin[l * 32 + 2 * j];
            float oa0 = q4.x * cs0.x - q4.y * sn0.x;   // out dim 2j
            float oa1 = q4.z * cs0.y - q4.w * sn0.y;   // out dim 2j+1
            float ob0 = q4.x * sn0.x + q4.y * cs0.x;   // out dim 32+2j
            float ob1 = q4.z * sn0.y + q4.w * cs0.y;   // out dim 32+2j+1
            float ha0 = bf_hi(oa0), ha1 = bf_hi(oa1);
            float hb0 = bf_hi(ob0), hb1 = bf_hi(ob1);
            QH[row * KWST + j]      = pack_bf(ha0, ha1);
            QL[row * KWST + j]      = pack_bf(oa0 - ha0, oa1 - ha1);
            QH[row * KWST + 16 + j] = pack_bf(hb0, hb1);
            QL[row * KWST + 16 + j] = pack_bf(ob0 - hb0, ob1 - hb1);
        }
    }
    __syncthreads();

    // --- Q fragments (hi and lo) to registers ---
    unsigned qh[4][4], ql[4][4];
    {
        const unsigned* QH = smu + AOFF_KH;
        const unsigned* QL = smu + AOFF_VH;
        int rA = w * 16 + g, rB = rA + 8;
#pragma unroll
        for (int ks = 0; ks < 4; ks++) {
            int c = ks * 8 + tg;
            qh[ks][0] = QH[rA * KWST + c];
            qh[ks][1] = QH[rB * KWST + c];
            qh[ks][2] = QH[rA * KWST + c + 4];
            qh[ks][3] = QH[rB * KWST + c + 4];
            ql[ks][0] = QL[rA * KWST + c];
            ql[ks][1] = QL[rB * KWST + c];
            ql[ks][2] = QL[rA * KWST + c + 4];
            ql[ks][3] = QL[rB * KWST + c + 4];
        }
    }

    float o[8][4];
#pragma unroll
    for (int ni = 0; ni < 8; ni++)
#pragma unroll
        for (int j = 0; j < 4; j++) o[ni][j] = 0.0f;
    float mA = -3.0e38f, mB = -3.0e38f, lA = 0.0f, lB = 0.0f;

    for (int kt = 0; kt < SEQ / BK; kt++) {
        int k0 = kt * BK;
        __syncthreads();  // readers of previous tile (and Q frags on iter 0) done
        {
            const float* Kg = g_K + (size_t)k0 * DM + h * HD;
            const float* Vg = g_V + (size_t)k0 * DM + h * HD;
            // K tile: rope + split, [row][dimword]
            for (int slot = tid; slot < 1024; slot += 256) {
                int row = slot >> 4, j = slot & 15;
                int l = k0 + row;
                float4 k4 = *(const float4*)&Kg[(size_t)row * DM + 4 * j];
                float2 cs0 = *(const float2*)&g_cos[l * 32 + 2 * j];
                float2 sn0 = *(const float2*)&g_sin[l * 32 + 2 * j];
                float oa0 = k4.x * cs0.x - k4.y * sn0.x;
                float oa1 = k4.z * cs0.y - k4.w * sn0.y;
                float ob0 = k4.x * sn0.x + k4.y * cs0.x;
                float ob1 = k4.z * sn0.y + k4.w * cs0.y;
                float ha0 = bf_hi(oa0), ha1 = bf_hi(oa1);
                float hb0 = bf_hi(ob0), hb1 = bf_hi(ob1);
                KH[row * KWST + j]      = pack_bf(ha0, ha1);
                KL[row * KWST + j]      = pack_bf(oa0 - ha0, oa1 - ha1);
                KH[row * KWST + 16 + j] = pack_bf(hb0, hb1);
                KL[row * KWST + 16 + j] = pack_bf(ob0 - hb0, ob1 - hb1);
            }
            // V tile: transposed key-pair packing, [kp][dim]
            for (int slot = tid; slot < 512; slot += 256) {
                int kp = slot >> 4, d4 = slot & 15;
                float4 va = *(const float4*)&Vg[(size_t)(2 * kp) * DM + 4 * d4];
                float4 vb = *(const float4*)&Vg[(size_t)(2 * kp + 1) * DM + 4 * d4];
                float af[4] = {va.x, va.y, va.z, va.w};
                float bf[4] = {vb.x, vb.y, vb.z, vb.w};
                unsigned wh[4], wl[4];
#pragma unroll
                for (int jj = 0; jj < 4; jj++) {
                    float hA = bf_hi(af[jj]), hB = bf_hi(bf[jj]);
                    wh[jj] = pack_bf(hA, hB);
                    wl[jj] = pack_bf(af[jj] - hA, bf[jj] - hB);
                }
                *(uint4*)&VH[kp * VWST + 4 * d4] = make_uint4(wh[0], wh[1], wh[2], wh[3]);
                *(uint4*)&VL[kp * VWST + 4 * d4] = make_uint4(wl[0], wl[1], wl[2], wl[3]);
            }
            if (tid < 64) MS[tid] = mask[k0 + tid];
        }
        __syncthreads();

        // --- S = Q . K^T ---
        float sacc[8][4];
#pragma unroll
        for (int ni = 0; ni < 8; ni++)
#pragma unroll
            for (int j = 0; j < 4; j++) sacc[ni][j] = 0.0f;

#pragma unroll
        for (int ks = 0; ks < 4; ks++) {
#pragma unroll
            for (int ni = 0; ni < 8; ni++) {
                int kr = ni * 8 + g;
                unsigned bh[2], bl[2];
                bh[0] = KH[kr * KWST + ks * 8 + tg];
                bh[1] = KH[kr * KWST + ks * 8 + tg + 4];
                bl[0] = KL[kr * KWST + ks * 8 + tg];
                bl[1] = KL[kr * KWST + ks * 8 + tg + 4];
                mma_bf16(sacc[ni], qh[ks], bh);
                mma_bf16(sacc[ni], ql[ks], bh);
                mma_bf16(sacc[ni], qh[ks], bl);
            }
        }

        // --- scale + mask ---
#pragma unroll
        for (int ni = 0; ni < 8; ni++) {
            int m0 = MS[ni * 8 + 2 * tg];
            int m1 = MS[ni * 8 + 2 * tg + 1];
            sacc[ni][0] = m0 ? sacc[ni][0] * 0.125f : -1.0e9f;
            sacc[ni][1] = m1 ? sacc[ni][1] * 0.125f : -1.0e9f;
            sacc[ni][2] = m0 ? sacc[ni][2] * 0.125f : -1.0e9f;
            sacc[ni][3] = m1 ? sacc[ni][3] * 0.125f : -1.0e9f;
        }

        // --- online softmax (rows g, g+8) ---
        float mxA = -3.0e38f, mxB = -3.0e38f;
#pragma unroll
        for (int ni = 0; ni < 8; ni++) {
            mxA = fmaxf(mxA, fmaxf(sacc[ni][0], sacc[ni][1]));
            mxB = fmaxf(mxB, fmaxf(sacc[ni][2], sacc[ni][3]));
        }
        mxA = fmaxf(mxA, __shfl_xor_sync(0xffffffffu, mxA, 1));
        mxA = fmaxf(mxA, __shfl_xor_sync(0xffffffffu, mxA, 2));
        mxB = fmaxf(mxB, __shfl_xor_sync(0xffffffffu, mxB, 1));
        mxB = fmaxf(mxB, __shfl_xor_sync(0xffffffffu, mxB, 2));

        float mnA = fmaxf(mA, mxA), mnB = fmaxf(mB, mxB);
        float corrA = exp2p((mA - mnA) * LOG2E);
        float corrB = exp2p((mB - mnB) * LOG2E);

        float sumA = 0.0f, sumB = 0.0f;
#pragma unroll
        for (int ni = 0; ni < 8; ni++) {
            sacc[ni][0] = exp2p((sacc[ni][0] - mnA) * LOG2E);
            sacc[ni][1] = exp2p((sacc[ni][1] - mnA) * LOG2E);
            sacc[ni][2] = exp2p((sacc[ni][2] - mnB) * LOG2E);
            sacc[ni][3] = exp2p((sacc[ni][3] - mnB) * LOG2E);
            sumA += sacc[ni][0] + sacc[ni][1];
            sumB += sacc[ni][2] + sacc[ni][3];
        }
        sumA += __shfl_xor_sync(0xffffffffu, sumA, 1);
        sumA += __shfl_xor_sync(0xffffffffu, sumA, 2);
        sumB += __shfl_xor_sync(0xffffffffu, sumB, 1);
        sumB += __shfl_xor_sync(0xffffffffu, sumB, 2);

        lA = lA * corrA + sumA;
        lB = lB * corrB + sumB;
        mA = mnA;
        mB = mnB;
#pragma unroll
        for (int ni = 0; ni < 8; ni++) {
            o[ni][0] *= corrA; o[ni][1] *= corrA;
            o[ni][2] *= corrB; o[ni][3] *= corrB;
        }

        // --- O += P . V : S C-frag == PV A-frag, split in registers ---
#pragma unroll
        for (int ks = 0; ks < 4; ks++) {
            unsigned ah[4], al[4];
#pragma unroll
            for (int half = 0; half < 2; half++) {
                const float* s2 = sacc[2 * ks + half];
                float h0 = bf_hi(s2[0]), h1 = bf_hi(s2[1]);
                float h2 = bf_hi(s2[2]), h3 = bf_hi(s2[3]);
                ah[2 * half]     = pack_bf(h0, h1);   // row g   (half? k-hi : k-lo)
                ah[2 * half + 1] = pack_bf(h2, h3);   // row g+8
                al[2 * half]     = pack_bf(s2[0] - h0, s2[1] - h1);
                al[2 * half + 1] = pack_bf(s2[2] - h2, s2[3] - h3);
            }
#pragma unroll
            for (int ni = 0; ni < 8; ni++) {
                int vr = ks * 8 + tg;
                unsigned bh[2], bl[2];
                bh[0] = VH[vr * VWST + ni * 8 + g];
                bh[1] = VH[(vr + 4) * VWST + ni * 8 + g];
                bl[0] = VL[vr * VWST + ni * 8 + g];
                bl[1] = VL[(vr + 4) * VWST + ni * 8 + g];
                mma_bf16(o[ni], ah, bh);
                mma_bf16(o[ni], al, bh);
                mma_bf16(o[ni], ah, bl);
            }
        }
    }

    // --- normalize + store ---
    float invA = 1.0f / lA, invB = 1.0f / lB;
    float* Og = g_att + (size_t)(q0 + w * 16) * DM + h * HD;
#pragma unroll
    for (int ni = 0; ni < 8; ni++) {
        *(float2*)&Og[(size_t)g * DM + ni * 8 + 2 * tg] =
            make_float2(o[ni][0] * invA, o[ni][1] * invA);
        *(float2*)&Og[(size_t)(g + 8) * DM + ni * 8 + 2 * tg] =
            make_float2(o[ni][2] * invB, o[ni][3] * invB);
    }
}

// ---------------------------------------------------------------------------
// launch
// ---------------------------------------------------------------------------
extern "C" void kernel_launch(void* const* d_in, const int* in_sizes, int n_in,
                              void* d_out, int out_size) {
    const float* x    = (const float*)d_in[0];
    const int*   mask = (const int*)d_in[1];
    const float* Wq   = (const float*)d_in[2];
    const float* Wk   = (const float*)d_in[3];
    const float* Wv   = (const float*)d_in[4];
    const float* Wo   = (const float*)d_in[5];
    float* out = (float*)d_out;

    rope_table_kernel<<<(SEQ * 32 + 255) / 256, 256>>>();
    gemm_qkv_kernel<<<dim3(16, 16, 3), 256>>>(x, Wq, Wk, Wv);

    attn_bf16_kernel<<<dim3(SEQ / BQ, NH), 256>>>(mask);

    gemm_out_kernel<<<dim3(16, 16), 256>>>(out, Wo);
}